// round 16
// baseline (speedup 1.0000x reference)
#include <cuda_runtime.h>
#include <cuda_bf16.h>
#include <math.h>

// Problem constants (fixed by reference): values [256, 262144] fp32.
// FINAL (converged): streaming sign-count at the chip's LTS/streaming ceiling
// (6433 GB/s measured, 80.4% of HBM spec); kernel 42.34us vs 41.7us pure-transfer
// floor at observed peak BW. Calibrated: unroll-8 optimum (MLP_p1 sweep
// 16/8/4 -> 42.98/42.40/42.72us), dual dp4a chains, REDUX.SUM warp reduce,
// fence-free packed-atomic epilogue (one 64b atomic per block, no init kernel).
#define B 256
#define N 262144
#define VEC4_PER_ROW (N / 4)          // 65536 int4 per row
#define BLOCKS_PER_ROW 16
#define THREADS 256
#define THREADS_PER_ROW (BLOCKS_PER_ROW * THREADS)        // 4096
#define VEC4_PER_THREAD (VEC4_PER_ROW / THREADS_PER_ROW)  // 16

// Per-row packed accumulator: low 32 bits = count0 sum, high 32 bits = #arrivals.
// ONE atomic per block (16 per row). The block taking the last arrival computes
// the row's entropy from the atomic return value (no fence, no partials array)
// and resets the word to 0 -> deterministic, graph-replay safe.
__device__ unsigned long long g_row_acc[B];

__device__ __forceinline__ int prmt_signbytes(int a, int b) {
    int r;
    // nibble 0xB = sign-replicate byte3 of a, 0xF = sign-replicate byte7 (b's byte3)
    asm("prmt.b32 %0, %1, %2, 0xFBFB;" : "=r"(r) : "r"(a), "r"(b));
    return r;
}

__device__ __forceinline__ int dp4a_acc(int a, int b, int c) {
    int r;
    asm("dp4a.s32.s32 %0, %1, %2, %3;" : "=r"(r) : "r"(a), "r"(b), "r"(c));
    return r;
}

__global__ void __launch_bounds__(THREADS) fused_entropy_kernel(
    const float* __restrict__ vals, float* __restrict__ out) {
    const int row = blockIdx.y;
    const int blk = blockIdx.x;
    const int4* __restrict__ p =
        reinterpret_cast<const int4*>(vals) + (size_t)row * VEC4_PER_ROW;

    const int base = blk * THREADS + threadIdx.x;

    // Two independent accumulator chains (halved dp4a dependency depth).
    // Each accumulates -(#sign-bit-set) over its half of the elements.
    int cnt_a = 0, cnt_b = 0;
#pragma unroll 8
    for (int k = 0; k < VEC4_PER_THREAD; ++k) {
        int4 v = __ldcs(&p[base + k * THREADS_PER_ROW]);  // read-once stream
        int s01 = prmt_signbytes(v.x, v.y);  // bytes0,1 = 0xFF if negative
        int s23 = prmt_signbytes(v.z, v.w);
        cnt_a = dp4a_acc(s01, 0x0101, cnt_a);  // -= negatives of x,y
        cnt_b = dp4a_acc(s23, 0x0101, cnt_b);  // -= negatives of z,w
    }
    int cnt = -(cnt_a + cnt_b);  // #negatives (count0) handled by this thread

    // warp reduce: single REDUX.SUM (sm_80+)
    cnt = __reduce_add_sync(0xFFFFFFFFu, cnt);

    // block reduce via smem (8 warps)
    __shared__ int warp_sums[THREADS / 32];
    if ((threadIdx.x & 31) == 0)
        warp_sums[threadIdx.x >> 5] = cnt;
    __syncthreads();

    if (threadIdx.x == 0) {
        int s = 0;
#pragma unroll
        for (int w = 0; w < THREADS / 32; ++w) s += warp_sums[w];

        // Single atomic: publish count AND take a ticket in one op.
        unsigned long long pkt = (1ULL << 32) | (unsigned long long)(unsigned)s;
        unsigned long long old = atomicAdd(&g_row_acc[row], pkt);
        unsigned arrivals_before = (unsigned)(old >> 32);

        if (arrivals_before == BLOCKS_PER_ROW - 1) {
            // This block completes the row: total count0 travelled through the atomic.
            unsigned c0 = (unsigned)old + (unsigned)s;

            const float n = (float)N;
            const float cc0 = (float)c0;
            const float cc1 = n - cc0;
            const float denom = n + 1e-8f;
            const float p0 = cc0 / denom;
            const float p1 = cc1 / denom;
            float t0 = (p0 > 0.0f) ? p0 * log2f(p0 + 1e-10f) : 0.0f;
            float t1 = (p1 > 0.0f) ? p1 * log2f(p1 + 1e-10f) : 0.0f;
            out[row] = -(t0 + t1);

            g_row_acc[row] = 0ULL;  // reset for next graph replay (deterministic)
        }
    }
}

extern "C" void kernel_launch(void* const* d_in, const int* in_sizes, int n_in,
                              void* d_out, int out_size) {
    const float* vals = (const float*)d_in[0];
    float* out = (float*)d_out;

    dim3 grid(BLOCKS_PER_ROW, B);
    fused_entropy_kernel<<<grid, THREADS>>>(vals, out);
}

// round 17
// speedup vs baseline: 1.0007x; 1.0007x over previous
#include <cuda_runtime.h>
#include <cuda_bf16.h>
#include <math.h>

// Problem constants (fixed by reference): values [256, 262144] fp32.
// FINAL (converged, 4x reproduced): streaming sign-count at the chip's
// LTS/streaming ceiling (6310-6433 GB/s measured, ~80% of HBM spec);
// kernel 42.3-42.5us vs 41.7us pure-transfer floor at observed peak BW.
// Calibrated: unroll-8 optimum (MLP_p1 sweep 16/8/4 -> 42.98/42.40/42.72us),
// dual dp4a chains, REDUX.SUM warp reduce, fence-free packed-atomic epilogue
// (one 64b atomic per block, no init kernel, graph-replay safe).
#define B 256
#define N 262144
#define VEC4_PER_ROW (N / 4)          // 65536 int4 per row
#define BLOCKS_PER_ROW 16
#define THREADS 256
#define THREADS_PER_ROW (BLOCKS_PER_ROW * THREADS)        // 4096
#define VEC4_PER_THREAD (VEC4_PER_ROW / THREADS_PER_ROW)  // 16

// Per-row packed accumulator: low 32 bits = count0 sum, high 32 bits = #arrivals.
// ONE atomic per block (16 per row). The block taking the last arrival computes
// the row's entropy from the atomic return value (no fence, no partials array)
// and resets the word to 0 -> deterministic, graph-replay safe.
__device__ unsigned long long g_row_acc[B];

__device__ __forceinline__ int prmt_signbytes(int a, int b) {
    int r;
    // nibble 0xB = sign-replicate byte3 of a, 0xF = sign-replicate byte7 (b's byte3)
    asm("prmt.b32 %0, %1, %2, 0xFBFB;" : "=r"(r) : "r"(a), "r"(b));
    return r;
}

__device__ __forceinline__ int dp4a_acc(int a, int b, int c) {
    int r;
    asm("dp4a.s32.s32 %0, %1, %2, %3;" : "=r"(r) : "r"(a), "r"(b), "r"(c));
    return r;
}

__global__ void __launch_bounds__(THREADS) fused_entropy_kernel(
    const float* __restrict__ vals, float* __restrict__ out) {
    const int row = blockIdx.y;
    const int blk = blockIdx.x;
    const int4* __restrict__ p =
        reinterpret_cast<const int4*>(vals) + (size_t)row * VEC4_PER_ROW;

    const int base = blk * THREADS + threadIdx.x;

    // Two independent accumulator chains (halved dp4a dependency depth).
    // Each accumulates -(#sign-bit-set) over its half of the elements.
    int cnt_a = 0, cnt_b = 0;
#pragma unroll 8
    for (int k = 0; k < VEC4_PER_THREAD; ++k) {
        int4 v = __ldcs(&p[base + k * THREADS_PER_ROW]);  // read-once stream
        int s01 = prmt_signbytes(v.x, v.y);  // bytes0,1 = 0xFF if negative
        int s23 = prmt_signbytes(v.z, v.w);
        cnt_a = dp4a_acc(s01, 0x0101, cnt_a);  // -= negatives of x,y
        cnt_b = dp4a_acc(s23, 0x0101, cnt_b);  // -= negatives of z,w
    }
    int cnt = -(cnt_a + cnt_b);  // #negatives (count0) handled by this thread

    // warp reduce: single REDUX.SUM (sm_80+)
    cnt = __reduce_add_sync(0xFFFFFFFFu, cnt);

    // block reduce via smem (8 warps)
    __shared__ int warp_sums[THREADS / 32];
    if ((threadIdx.x & 31) == 0)
        warp_sums[threadIdx.x >> 5] = cnt;
    __syncthreads();

    if (threadIdx.x == 0) {
        int s = 0;
#pragma unroll
        for (int w = 0; w < THREADS / 32; ++w) s += warp_sums[w];

        // Single atomic: publish count AND take a ticket in one op.
        unsigned long long pkt = (1ULL << 32) | (unsigned long long)(unsigned)s;
        unsigned long long old = atomicAdd(&g_row_acc[row], pkt);
        unsigned arrivals_before = (unsigned)(old >> 32);

        if (arrivals_before == BLOCKS_PER_ROW - 1) {
            // This block completes the row: total count0 travelled through the atomic.
            unsigned c0 = (unsigned)old + (unsigned)s;

            const float n = (float)N;
            const float cc0 = (float)c0;
            const float cc1 = n - cc0;
            const float denom = n + 1e-8f;
            const float p0 = cc0 / denom;
            const float p1 = cc1 / denom;
            float t0 = (p0 > 0.0f) ? p0 * log2f(p0 + 1e-10f) : 0.0f;
            float t1 = (p1 > 0.0f) ? p1 * log2f(p1 + 1e-10f) : 0.0f;
            out[row] = -(t0 + t1);

            g_row_acc[row] = 0ULL;  // reset for next graph replay (deterministic)
        }
    }
}

extern "C" void kernel_launch(void* const* d_in, const int* in_sizes, int n_in,
                              void* d_out, int out_size) {
    const float* vals = (const float*)d_in[0];
    float* out = (float*)d_out;

    dim3 grid(BLOCKS_PER_ROW, B);
    fused_entropy_kernel<<<grid, THREADS>>>(vals, out);
}